// round 11
// baseline (speedup 1.0000x reference)
#include <cuda_runtime.h>
#include <cuda_bf16.h>
#include <cuda_fp16.h>
#include <cstdint>

#define N_NODES 100000
#define MAX_E   800000
#define HID     256
#define NB_SCAN 98          // ceil(100000/1024)

// ---- scratch (static __device__ globals; no allocation) ----
__device__ __align__(16) __half g_h[(size_t)N_NODES * HID];   // layer output / x16, fp16
__device__ __align__(16) __half g_a[(size_t)N_NODES * HID];   // agg output = GEMM A, fp16
__device__ __align__(16) __half g_wt[HID * HID];              // W^T [256, K] fp16
__device__ float g_dinv[N_NODES];
__device__ int   g_cnt[N_NODES];
__device__ int   g_cur[N_NODES];
__device__ int   g_rowptr[N_NODES + 1];
__device__ int   g_col[MAX_E];
__device__ int   g_part[128];

// ================= PTX helpers (base-target only: ldmatrix/mma/cp.async) =================
__device__ __forceinline__ uint32_t smem_u32(const void* p) {
    uint32_t a;
    asm("{ .reg .u64 t; cvta.to.shared.u64 t, %1; cvt.u32.u64 %0, t; }" : "=r"(a) : "l"(p));
    return a;
}
__device__ __forceinline__ void ldsm_x4(uint32_t* r, uint32_t addr) {
    asm volatile("ldmatrix.sync.aligned.m8n8.x4.shared.b16 {%0,%1,%2,%3}, [%4];"
        : "=r"(r[0]), "=r"(r[1]), "=r"(r[2]), "=r"(r[3]) : "r"(addr));
}
__device__ __forceinline__ void ldsm_x2(uint32_t* r, uint32_t addr) {
    asm volatile("ldmatrix.sync.aligned.m8n8.x2.shared.b16 {%0,%1}, [%2];"
        : "=r"(r[0]), "=r"(r[1]) : "r"(addr));
}
__device__ __forceinline__ void mma_f16(float* c, const uint32_t* a, const uint32_t* b) {
    asm volatile("mma.sync.aligned.m16n8k16.row.col.f32.f16.f16.f32 "
        "{%0,%1,%2,%3}, {%4,%5,%6,%7}, {%8,%9}, {%0,%1,%2,%3};"
        : "+f"(c[0]), "+f"(c[1]), "+f"(c[2]), "+f"(c[3])
        : "r"(a[0]), "r"(a[1]), "r"(a[2]), "r"(a[3]), "r"(b[0]), "r"(b[1]));
}
__device__ __forceinline__ void cp16(uint32_t dst, const void* src) {
    asm volatile("cp.async.cg.shared.global [%0], [%1], 16;" :: "r"(dst), "l"(src));
}
#define CP_COMMIT() asm volatile("cp.async.commit_group;" ::: "memory")
#define CP_WAIT0()  asm volatile("cp.async.wait_group 0;" ::: "memory")

// ================= preprocessing =================
__global__ void init_kernel() {
    int i = blockIdx.x * blockDim.x + threadIdx.x;
    if (i < N_NODES) { g_cnt[i] = 0; g_cur[i] = 0; }
}
__global__ void count_kernel(const int* __restrict__ dst, int E) {
    int e = blockIdx.x * blockDim.x + threadIdx.x;
    if (e < E) {
        int d = dst[e];
        if (d >= 0 && d < N_NODES) atomicAdd(&g_cnt[d], 1);
    }
}
__global__ void dinv_kernel() {
    int i = blockIdx.x * blockDim.x + threadIdx.x;
    if (i < N_NODES) g_dinv[i] = rsqrtf((float)g_cnt[i] + 1.0f);
}
__global__ void scan_reduce_kernel() {
    __shared__ int ws[32];
    int t = threadIdx.x, lane = t & 31, wid = t >> 5;
    int i = blockIdx.x * 1024 + t;
    int v = (i < N_NODES) ? g_cnt[i] : 0;
    #pragma unroll
    for (int o = 16; o > 0; o >>= 1) v += __shfl_down_sync(0xffffffffu, v, o);
    if (lane == 0) ws[wid] = v;
    __syncthreads();
    if (wid == 0) {
        int s = ws[lane];
        #pragma unroll
        for (int o = 16; o > 0; o >>= 1) s += __shfl_down_sync(0xffffffffu, s, o);
        if (lane == 0) g_part[blockIdx.x] = s;
    }
}
__global__ void scan_part_kernel() {
    __shared__ int ws[4];
    int t = threadIdx.x, lane = t & 31, wid = t >> 5;
    int v = (t < NB_SCAN) ? g_part[t] : 0;
    int incl = v;
    #pragma unroll
    for (int o = 1; o < 32; o <<= 1) {
        int n = __shfl_up_sync(0xffffffffu, incl, o);
        if (lane >= o) incl += n;
    }
    if (lane == 31) ws[wid] = incl;
    __syncthreads();
    int off = 0;
    for (int j = 0; j < wid; j++) off += ws[j];
    if (t < NB_SCAN) g_part[t] = off + incl - v;   // exclusive
}
__global__ void scan_apply_kernel() {
    __shared__ int ws[32];
    int t = threadIdx.x, lane = t & 31, wid = t >> 5;
    int i = blockIdx.x * 1024 + t;
    int v = (i < N_NODES) ? g_cnt[i] : 0;
    int incl = v;
    #pragma unroll
    for (int o = 1; o < 32; o <<= 1) {
        int n = __shfl_up_sync(0xffffffffu, incl, o);
        if (lane >= o) incl += n;
    }
    if (lane == 31) ws[wid] = incl;
    __syncthreads();
    if (wid == 0) {
        int wv = ws[lane];
        #pragma unroll
        for (int o = 1; o < 32; o <<= 1) {
            int n = __shfl_up_sync(0xffffffffu, wv, o);
            if (lane >= o) wv += n;
        }
        ws[lane] = wv;
    }
    __syncthreads();
    int pre = (wid > 0) ? ws[wid - 1] : 0;
    if (i < N_NODES) g_rowptr[i + 1] = g_part[blockIdx.x] + pre + incl;
    if (i == 0) g_rowptr[0] = 0;
}
__global__ void scatter_kernel(const int* __restrict__ src,
                               const int* __restrict__ dst, int E) {
    int e = blockIdx.x * blockDim.x + threadIdx.x;
    if (e < E) {
        int d = dst[e];
        int s = src[e];
        if (d >= 0 && d < N_NODES && s >= 0 && s < N_NODES) {
            int p = atomicAdd(&g_cur[d], 1);
            g_col[g_rowptr[d] + p] = s;
        }
    }
}

// ================= x fp32 -> fp16 (into g_h, 128 cols) =================
__global__ void xconv_kernel(const float* __restrict__ x) {
    int i = blockIdx.x * blockDim.x + threadIdx.x;   // float4 index
    if (i < N_NODES * 128 / 4) {
        float4 f = *(const float4*)(x + (size_t)i * 4);
        __half2 h0 = __floats2half2_rn(f.x, f.y);
        __half2 h1 = __floats2half2_rn(f.z, f.w);
        uint2 o;
        o.x = *(uint32_t*)&h0;
        o.y = *(uint32_t*)&h1;
        *(uint2*)(g_h + (size_t)i * 4) = o;
    }
}

// ================= W transpose -> fp16 =================
__global__ void wconv_kernel(const float* __restrict__ W, int K) {
    int idx = blockIdx.x * blockDim.x + threadIdx.x;
    if (idx < HID * K) {
        int n = idx / K, k = idx % K;
        g_wt[idx] = __float2half_rn(W[(size_t)k * HID + n]);
    }
}

// ================= aggregation: g_a = fp16(A_norm @ act(g_h)) =================
// warp-per-node; input always g_h fp16 (x pre-converted)
template<int COLS, bool RELU>
__global__ void agg_kernel() {
    int gw   = (blockIdx.x * blockDim.x + threadIdx.x) >> 5;
    int lane = threadIdx.x & 31;
    if (gw >= N_NODES) return;
    constexpr int V = COLS / 32;          // elems per lane: 4 (128) or 8 (256)
    float acc[V];
    #pragma unroll
    for (int q = 0; q < V; q++) acc[q] = 0.f;
    const int base = lane * V;
    int rs = __ldg(&g_rowptr[gw]);
    int re = __ldg(&g_rowptr[gw + 1]);

    auto fetch = [&](int s, float vv[V]) {
        const __half* p = g_h + (size_t)s * COLS + base;
        if (V == 8) {
            uint4 raw = *(const uint4*)p;
            const __half2* h2 = reinterpret_cast<const __half2*>(&raw);
            #pragma unroll
            for (int j = 0; j < 4; j++) {
                float2 f = __half22float2(h2[j]);
                vv[2 * j] = f.x; vv[2 * j + 1] = f.y;
            }
        } else {
            uint2 raw = *(const uint2*)p;
            const __half2* h2 = reinterpret_cast<const __half2*>(&raw);
            #pragma unroll
            for (int j = 0; j < 2; j++) {
                float2 f = __half22float2(h2[j]);
                vv[2 * j] = f.x; vv[2 * j + 1] = f.y;
            }
        }
        if (RELU) {
            #pragma unroll
            for (int q = 0; q < V; q++) vv[q] = fmaxf(vv[q], 0.f);
        }
    };

    int e = rs;
    for (; e + 3 < re; e += 4) {
        int s0 = g_col[e], s1 = g_col[e + 1], s2 = g_col[e + 2], s3 = g_col[e + 3];
        float w0 = g_dinv[s0], w1 = g_dinv[s1], w2 = g_dinv[s2], w3 = g_dinv[s3];
        float v0[V], v1[V], v2[V], v3[V];
        fetch(s0, v0); fetch(s1, v1); fetch(s2, v2); fetch(s3, v3);
        #pragma unroll
        for (int q = 0; q < V; q++)
            acc[q] += (w0 * v0[q] + w1 * v1[q]) + (w2 * v2[q] + w3 * v3[q]);
    }
    for (; e < re; e++) {
        int   s = g_col[e];
        float w = g_dinv[s];
        float v[V];
        fetch(s, v);
        #pragma unroll
        for (int q = 0; q < V; q++) acc[q] += w * v[q];
    }
    float di = g_dinv[gw];
    {
        float v[V];
        fetch(gw, v);
        #pragma unroll
        for (int q = 0; q < V; q++) acc[q] += di * v[q];
    }
    __half2 o[V / 2];
    #pragma unroll
    for (int q = 0; q < V / 2; q++)
        o[q] = __floats2half2_rn(acc[2 * q] * di, acc[2 * q + 1] * di);
    __half* po = g_a + (size_t)gw * COLS + base;
    if (V == 8)      *(uint4*)po = *(const uint4*)o;
    else             *(uint2*)po = *(const uint2*)o;
}

// ================= HMMA fp16 GEMM, CTA 128x256 (full N), cp.async 2-stage =================
// 512 threads = 16 warps (4m x 4n), warp tile 32x64, BK=32
#define BKP        40                       // padded K stride (halves): 80 B
#define A_BYTES    (128 * BKP * 2)          // 10240 B
#define B_BYTES    (256 * BKP * 2)          // 20480 B
#define STG_BYTES  (A_BYTES + B_BYTES)      // 30720 B
#define GEMM_SMEM  (2 * STG_BYTES)          // 61440 B

template<int K, bool WRITE_HALF>
__global__ __launch_bounds__(512, 1)
void gemm_mma_kernel(const float* __restrict__ bias, float* __restrict__ C_ext) {
    extern __shared__ __align__(16) char dsm[];
    const int M   = N_NODES;
    const int tid = threadIdx.x;
    const int wid = tid >> 5, lane = tid & 31;
    const int bm  = blockIdx.x * 128;
    const int warp_m = wid & 3;          // 4 tiles of 32 rows
    const int warp_n = wid >> 2;         // 4 tiles of 64 cols
    constexpr int NCH = K / 32;

    const uint32_t sb = smem_u32(dsm);
    // A: 512 slots (128 rows x 4 segs), 1 per thread
    const int ra = tid >> 2, sa = tid & 3;
    // B: 1024 slots (256 rows x 4 segs), 2 per thread
    const int rb0 = tid >> 2,          sb0 = tid & 3;
    const int rb1 = (tid + 512) >> 2,  sb1 = tid & 3;     // rb1 = rb0 + 128

    float acc[2][8][4];
    #pragma unroll
    for (int mt = 0; mt < 2; mt++)
        #pragma unroll
        for (int nt = 0; nt < 8; nt++)
            #pragma unroll
            for (int q = 0; q < 4; q++) acc[mt][nt][q] = 0.f;

    const int a_row = warp_m * 32 + (lane & 15);
    const int a_kof = (lane >> 4) * 8;
    const int b_row = warp_n * 64 + (lane & 7);
    const int b_kof = ((lane >> 3) & 1) * 8;

    int gra = bm + ra; if (gra > M - 1) gra = M - 1;

    auto issue = [&](int c, int st) {
        const int k0 = c * 32;
        uint32_t base = sb + st * STG_BYTES;
        cp16(base + (uint32_t)(ra * BKP + sa * 8) * 2,
             &g_a[(size_t)gra * K + k0 + sa * 8]);
        uint32_t bB = base + A_BYTES;
        cp16(bB + (uint32_t)(rb0 * BKP + sb0 * 8) * 2,
             &g_wt[(size_t)rb0 * K + k0 + sb0 * 8]);
        cp16(bB + (uint32_t)(rb1 * BKP + sb1 * 8) * 2,
             &g_wt[(size_t)rb1 * K + k0 + sb1 * 8]);
        CP_COMMIT();
    };

    issue(0, 0);
    for (int c = 0; c < NCH; c++) {
        const int st = c & 1;
        CP_WAIT0();
        __syncthreads();
        if (c + 1 < NCH) issue(c + 1, st ^ 1);

        uint32_t base = sb + st * STG_BYTES;
        uint32_t bA = base;
        uint32_t bB = base + A_BYTES;
        #pragma unroll
        for (int ks = 0; ks < 32; ks += 16) {
            uint32_t af[2][4];
            #pragma unroll
            for (int mt = 0; mt < 2; mt++) {
                uint32_t off = (uint32_t)((a_row + mt * 16) * BKP + ks + a_kof) * 2;
                ldsm_x4(af[mt], bA + off);
            }
            #pragma unroll
            for (int nt = 0; nt < 8; nt++) {
                uint32_t off = (uint32_t)((b_row + nt * 8) * BKP + ks + b_kof) * 2;
                uint32_t bf[2];
                ldsm_x2(bf, bB + off);
                #pragma unroll
                for (int mt = 0; mt < 2; mt++)
                    mma_f16(acc[mt][nt], af[mt], bf);
            }
        }
        __syncthreads();
    }

    const int er = lane >> 2;
    const int ec = (lane & 3) * 2;
    #pragma unroll
    for (int nt = 0; nt < 8; nt++) {
        int col = warp_n * 64 + nt * 8 + ec;
        float bx = bias[col], by = bias[col + 1];
        #pragma unroll
        for (int mt = 0; mt < 2; mt++) {
            int r = bm + warp_m * 32 + mt * 16 + er;
            if (r < M) {
                float cx = acc[mt][nt][0] + bx, cy = acc[mt][nt][1] + by;
                if (WRITE_HALF) *(__half2*)&g_h[(size_t)r * HID + col] = __floats2half2_rn(cx, cy);
                else            *(float2*)&C_ext[(size_t)r * HID + col] = make_float2(cx, cy);
            }
            if (r + 8 < M) {
                float cx = acc[mt][nt][2] + bx, cy = acc[mt][nt][3] + by;
                if (WRITE_HALF) *(__half2*)&g_h[(size_t)(r + 8) * HID + col] = __floats2half2_rn(cx, cy);
                else            *(float2*)&C_ext[(size_t)(r + 8) * HID + col] = make_float2(cx, cy);
            }
        }
    }
}

// ================= launch =================
extern "C" void kernel_launch(void* const* d_in, const int* in_sizes, int n_in,
                              void* d_out, int out_size) {
    const float* x   = (const float*)d_in[0];
    const int*   ei  = (const int*)d_in[1];
    const float* W1  = (const float*)d_in[2];
    const float* b1  = (const float*)d_in[3];
    const float* W2  = (const float*)d_in[4];
    const float* b2  = (const float*)d_in[5];
    const float* W3  = (const float*)d_in[6];
    const float* b3  = (const float*)d_in[7];
    float*       out = (float*)d_out;

    const int E = in_sizes[1] / 2;
    const int* src = ei;
    const int* dst = ei + E;

    static bool attr_done = false;
    if (!attr_done) {
        cudaFuncSetAttribute(gemm_mma_kernel<128, true>,  cudaFuncAttributeMaxDynamicSharedMemorySize, GEMM_SMEM);
        cudaFuncSetAttribute(gemm_mma_kernel<256, true>,  cudaFuncAttributeMaxDynamicSharedMemorySize, GEMM_SMEM);
        cudaFuncSetAttribute(gemm_mma_kernel<256, false>, cudaFuncAttributeMaxDynamicSharedMemorySize, GEMM_SMEM);
        attr_done = true;
    }

    const int TB = 256;
    const int nb_nodes = (N_NODES + TB - 1) / TB;
    const int nb_edges = (E + TB - 1) / TB;
    const int nb_agg   = (N_NODES * 32 + TB - 1) / TB;
    const int gemm_grid = (N_NODES + 127) / 128;

    // preprocessing: CSR + dinv (parallel scan)
    init_kernel<<<nb_nodes, TB>>>();
    count_kernel<<<nb_edges, TB>>>(dst, E);
    dinv_kernel<<<nb_nodes, TB>>>();
    scan_reduce_kernel<<<NB_SCAN, 1024>>>();
    scan_part_kernel<<<1, 128>>>();
    scan_apply_kernel<<<NB_SCAN, 1024>>>();
    scatter_kernel<<<nb_edges, TB>>>(src, dst, E);

    // layer 1: x -> g_h fp16; agg -> g_a; gemm K=128 -> g_h
    xconv_kernel<<<(N_NODES * 128 / 4 + TB - 1) / TB, TB>>>(x);
    wconv_kernel<<<(HID * 128 + 255) / 256, 256>>>(W1, 128);
    agg_kernel<128, false><<<nb_agg, TB>>>();
    gemm_mma_kernel<128, true><<<gemm_grid, 512, GEMM_SMEM>>>(b1, nullptr);
    // layer 2
    wconv_kernel<<<(HID * 256 + 255) / 256, 256>>>(W2, 256);
    agg_kernel<256, true><<<nb_agg, TB>>>();
    gemm_mma_kernel<256, true><<<gemm_grid, 512, GEMM_SMEM>>>(b2, nullptr);
    // layer 3
    wconv_kernel<<<(HID * 256 + 255) / 256, 256>>>(W3, 256);
    agg_kernel<256, true><<<nb_agg, TB>>>();
    gemm_mma_kernel<256, false><<<gemm_grid, 512, GEMM_SMEM>>>(b3, out);
}

// round 12
// speedup vs baseline: 1.0096x; 1.0096x over previous
#include <cuda_runtime.h>
#include <cuda_bf16.h>
#include <cuda_fp16.h>
#include <cstdint>

#define N_NODES 100000
#define MAX_E   800000
#define HID     256
#define NB_SCAN 98          // ceil(100000/1024)

// ---- scratch (static __device__ globals; no allocation) ----
__device__ __align__(16) __half g_h[(size_t)N_NODES * HID];   // layer output / x16, fp16
__device__ __align__(16) __half g_a[(size_t)N_NODES * HID];   // agg output = GEMM A, fp16
__device__ __align__(16) __half g_wt[HID * HID];              // W^T [256, K] fp16
__device__ float g_dinv[N_NODES];
__device__ int   g_cnt[N_NODES];
__device__ int   g_cur[N_NODES];
__device__ int   g_rowptr[N_NODES + 1];
__device__ int   g_col[MAX_E];
__device__ int   g_part[128];

// ================= PTX helpers (base-target only: ldmatrix/mma/cp.async) =================
__device__ __forceinline__ uint32_t smem_u32(const void* p) {
    uint32_t a;
    asm("{ .reg .u64 t; cvta.to.shared.u64 t, %1; cvt.u32.u64 %0, t; }" : "=r"(a) : "l"(p));
    return a;
}
__device__ __forceinline__ void ldsm_x4(uint32_t* r, uint32_t addr) {
    asm volatile("ldmatrix.sync.aligned.m8n8.x4.shared.b16 {%0,%1,%2,%3}, [%4];"
        : "=r"(r[0]), "=r"(r[1]), "=r"(r[2]), "=r"(r[3]) : "r"(addr));
}
__device__ __forceinline__ void mma_f16(float* c, const uint32_t* a, const uint32_t* b) {
    asm volatile("mma.sync.aligned.m16n8k16.row.col.f32.f16.f16.f32 "
        "{%0,%1,%2,%3}, {%4,%5,%6,%7}, {%8,%9}, {%0,%1,%2,%3};"
        : "+f"(c[0]), "+f"(c[1]), "+f"(c[2]), "+f"(c[3])
        : "r"(a[0]), "r"(a[1]), "r"(a[2]), "r"(a[3]), "r"(b[0]), "r"(b[1]));
}
__device__ __forceinline__ void cp16(uint32_t dst, const void* src) {
    asm volatile("cp.async.cg.shared.global [%0], [%1], 16;" :: "r"(dst), "l"(src));
}
#define CP_COMMIT() asm volatile("cp.async.commit_group;" ::: "memory")
#define CP_WAIT0()  asm volatile("cp.async.wait_group 0;" ::: "memory")

// ================= preprocessing =================
__global__ void init_kernel() {
    int i = blockIdx.x * blockDim.x + threadIdx.x;
    if (i < N_NODES) { g_cnt[i] = 0; g_cur[i] = 0; }
}
__global__ void count_kernel(const int* __restrict__ dst, int E) {
    int e = blockIdx.x * blockDim.x + threadIdx.x;
    if (e < E) {
        int d = dst[e];
        if (d >= 0 && d < N_NODES) atomicAdd(&g_cnt[d], 1);
    }
}
__global__ void dinv_kernel() {
    int i = blockIdx.x * blockDim.x + threadIdx.x;
    if (i < N_NODES) g_dinv[i] = rsqrtf((float)g_cnt[i] + 1.0f);
}
__global__ void scan_reduce_kernel() {
    __shared__ int ws[32];
    int t = threadIdx.x, lane = t & 31, wid = t >> 5;
    int i = blockIdx.x * 1024 + t;
    int v = (i < N_NODES) ? g_cnt[i] : 0;
    #pragma unroll
    for (int o = 16; o > 0; o >>= 1) v += __shfl_down_sync(0xffffffffu, v, o);
    if (lane == 0) ws[wid] = v;
    __syncthreads();
    if (wid == 0) {
        int s = ws[lane];
        #pragma unroll
        for (int o = 16; o > 0; o >>= 1) s += __shfl_down_sync(0xffffffffu, s, o);
        if (lane == 0) g_part[blockIdx.x] = s;
    }
}
__global__ void scan_part_kernel() {
    __shared__ int ws[4];
    int t = threadIdx.x, lane = t & 31, wid = t >> 5;
    int v = (t < NB_SCAN) ? g_part[t] : 0;
    int incl = v;
    #pragma unroll
    for (int o = 1; o < 32; o <<= 1) {
        int n = __shfl_up_sync(0xffffffffu, incl, o);
        if (lane >= o) incl += n;
    }
    if (lane == 31) ws[wid] = incl;
    __syncthreads();
    int off = 0;
    for (int j = 0; j < wid; j++) off += ws[j];
    if (t < NB_SCAN) g_part[t] = off + incl - v;   // exclusive
}
__global__ void scan_apply_kernel() {
    __shared__ int ws[32];
    int t = threadIdx.x, lane = t & 31, wid = t >> 5;
    int i = blockIdx.x * 1024 + t;
    int v = (i < N_NODES) ? g_cnt[i] : 0;
    int incl = v;
    #pragma unroll
    for (int o = 1; o < 32; o <<= 1) {
        int n = __shfl_up_sync(0xffffffffu, incl, o);
        if (lane >= o) incl += n;
    }
    if (lane == 31) ws[wid] = incl;
    __syncthreads();
    if (wid == 0) {
        int wv = ws[lane];
        #pragma unroll
        for (int o = 1; o < 32; o <<= 1) {
            int n = __shfl_up_sync(0xffffffffu, wv, o);
            if (lane >= o) wv += n;
        }
        ws[lane] = wv;
    }
    __syncthreads();
    int pre = (wid > 0) ? ws[wid - 1] : 0;
    if (i < N_NODES) g_rowptr[i + 1] = g_part[blockIdx.x] + pre + incl;
    if (i == 0) g_rowptr[0] = 0;
}
__global__ void scatter_kernel(const int* __restrict__ src,
                               const int* __restrict__ dst, int E) {
    int e = blockIdx.x * blockDim.x + threadIdx.x;
    if (e < E) {
        int d = dst[e];
        int s = src[e];
        if (d >= 0 && d < N_NODES && s >= 0 && s < N_NODES) {
            int p = atomicAdd(&g_cur[d], 1);
            g_col[g_rowptr[d] + p] = s;
        }
    }
}

// ================= x fp32 -> fp16 (into g_h, 128 cols) =================
__global__ void xconv_kernel(const float* __restrict__ x) {
    int i = blockIdx.x * blockDim.x + threadIdx.x;   // float4 index
    if (i < N_NODES * 128 / 4) {
        float4 f = *(const float4*)(x + (size_t)i * 4);
        __half2 h0 = __floats2half2_rn(f.x, f.y);
        __half2 h1 = __floats2half2_rn(f.z, f.w);
        uint2 o;
        o.x = *(uint32_t*)&h0;
        o.y = *(uint32_t*)&h1;
        *(uint2*)(g_h + (size_t)i * 4) = o;
    }
}

// ================= W transpose -> fp16 =================
__global__ void wconv_kernel(const float* __restrict__ W, int K) {
    int idx = blockIdx.x * blockDim.x + threadIdx.x;
    if (idx < HID * K) {
        int n = idx / K, k = idx % K;
        g_wt[idx] = __float2half_rn(W[(size_t)k * HID + n]);
    }
}

// ================= aggregation: g_a = fp16(A_norm @ act(g_h)) =================
// warp-per-node; input always g_h fp16 (x pre-converted)
template<int COLS, bool RELU>
__global__ void agg_kernel() {
    int gw   = (blockIdx.x * blockDim.x + threadIdx.x) >> 5;
    int lane = threadIdx.x & 31;
    if (gw >= N_NODES) return;
    constexpr int V = COLS / 32;          // elems per lane: 4 (128) or 8 (256)
    float acc[V];
    #pragma unroll
    for (int q = 0; q < V; q++) acc[q] = 0.f;
    const int base = lane * V;
    int rs = __ldg(&g_rowptr[gw]);
    int re = __ldg(&g_rowptr[gw + 1]);

    auto fetch = [&](int s, float vv[V]) {
        const __half* p = g_h + (size_t)s * COLS + base;
        if (V == 8) {
            uint4 raw = *(const uint4*)p;
            const __half2* h2 = reinterpret_cast<const __half2*>(&raw);
            #pragma unroll
            for (int j = 0; j < 4; j++) {
                float2 f = __half22float2(h2[j]);
                vv[2 * j] = f.x; vv[2 * j + 1] = f.y;
            }
        } else {
            uint2 raw = *(const uint2*)p;
            const __half2* h2 = reinterpret_cast<const __half2*>(&raw);
            #pragma unroll
            for (int j = 0; j < 2; j++) {
                float2 f = __half22float2(h2[j]);
                vv[2 * j] = f.x; vv[2 * j + 1] = f.y;
            }
        }
        if (RELU) {
            #pragma unroll
            for (int q = 0; q < V; q++) vv[q] = fmaxf(vv[q], 0.f);
        }
    };

    int e = rs;
    for (; e + 3 < re; e += 4) {
        int s0 = g_col[e], s1 = g_col[e + 1], s2 = g_col[e + 2], s3 = g_col[e + 3];
        float w0 = g_dinv[s0], w1 = g_dinv[s1], w2 = g_dinv[s2], w3 = g_dinv[s3];
        float v0[V], v1[V], v2[V], v3[V];
        fetch(s0, v0); fetch(s1, v1); fetch(s2, v2); fetch(s3, v3);
        #pragma unroll
        for (int q = 0; q < V; q++)
            acc[q] += (w0 * v0[q] + w1 * v1[q]) + (w2 * v2[q] + w3 * v3[q]);
    }
    for (; e < re; e++) {
        int   s = g_col[e];
        float w = g_dinv[s];
        float v[V];
        fetch(s, v);
        #pragma unroll
        for (int q = 0; q < V; q++) acc[q] += w * v[q];
    }
    float di = g_dinv[gw];
    {
        float v[V];
        fetch(gw, v);
        #pragma unroll
        for (int q = 0; q < V; q++) acc[q] += di * v[q];
    }
    __half2 o[V / 2];
    #pragma unroll
    for (int q = 0; q < V / 2; q++)
        o[q] = __floats2half2_rn(acc[2 * q] * di, acc[2 * q + 1] * di);
    __half* po = g_a + (size_t)gw * COLS + base;
    if (V == 8)      *(uint4*)po = *(const uint4*)o;
    else             *(uint2*)po = *(const uint2*)o;
}

// ================= HMMA fp16 GEMM, CTA 128x128, cp.async 2-stage (round-9 shape) =================
// 256 threads = 8 warps (4m x 2n), warp tile 32x64, BK=32; B frags via ldmatrix.x4
#define BKP       40                        // padded K stride (halves): 80 B
#define BUF_BYTES (128 * BKP * 2)           // 10240 B
#define STG_BYTES (2 * BUF_BYTES)           // A, B
#define GEMM_SMEM (2 * STG_BYTES)           // 40960 B -> 2 CTAs/SM

template<int K, bool WRITE_HALF>
__global__ __launch_bounds__(256)
void gemm_mma_kernel(const float* __restrict__ bias, float* __restrict__ C_ext) {
    extern __shared__ __align__(16) char dsm[];
    const int M   = N_NODES;
    const int tid = threadIdx.x;
    const int wid = tid >> 5, lane = tid & 31;
    const int bm  = blockIdx.x * 128;
    const int bn  = blockIdx.y * 128;
    const int warp_m = wid & 3;
    const int warp_n = wid >> 2;
    constexpr int NCH = K / 32;

    const uint32_t sb = smem_u32(dsm);
    const int r0 = tid >> 2, s0 = tid & 3;
    const int r1 = r0 + 64;

    float acc[2][8][4];
    #pragma unroll
    for (int mt = 0; mt < 2; mt++)
        #pragma unroll
        for (int nt = 0; nt < 8; nt++)
            #pragma unroll
            for (int q = 0; q < 4; q++) acc[mt][nt][q] = 0.f;

    const int a_row  = warp_m * 32 + (lane & 15);
    const int a_kof  = (lane >> 4) * 8;
    // B x4 lane map: lanes 0-7 -> rows n0-7 klo, 8-15 -> n0-7 khi, 16-23 -> n8-15 klo, 24-31 -> n8-15 khi
    const int b_row4 = warp_n * 64 + (lane & 7) + ((lane >> 4) << 3);
    const int b_kof  = ((lane >> 3) & 1) * 8;

    int gr0 = bm + r0; if (gr0 > M - 1) gr0 = M - 1;
    int gr1 = bm + r1; if (gr1 > M - 1) gr1 = M - 1;

    auto issue = [&](int c, int st) {
        const int k0 = c * 32;
        uint32_t base = sb + st * STG_BYTES;
        uint32_t o0 = (uint32_t)(r0 * BKP + s0 * 8) * 2;
        uint32_t o1 = (uint32_t)(r1 * BKP + s0 * 8) * 2;
        cp16(base + 0 * BUF_BYTES + o0, &g_a[(size_t)gr0 * K + k0 + s0 * 8]);
        cp16(base + 0 * BUF_BYTES + o1, &g_a[(size_t)gr1 * K + k0 + s0 * 8]);
        cp16(base + 1 * BUF_BYTES + o0, &g_wt[(size_t)(bn + r0) * K + k0 + s0 * 8]);
        cp16(base + 1 * BUF_BYTES + o1, &g_wt[(size_t)(bn + r1) * K + k0 + s0 * 8]);
        CP_COMMIT();
    };

    issue(0, 0);
    for (int c = 0; c < NCH; c++) {
        const int st = c & 1;
        CP_WAIT0();
        __syncthreads();
        if (c + 1 < NCH) issue(c + 1, st ^ 1);

        uint32_t base = sb + st * STG_BYTES;
        uint32_t bA = base;
        uint32_t bB = base + BUF_BYTES;
        #pragma unroll
        for (int ks = 0; ks < 32; ks += 16) {
            uint32_t af[2][4];
            #pragma unroll
            for (int mt = 0; mt < 2; mt++) {
                uint32_t off = (uint32_t)((a_row + mt * 16) * BKP + ks + a_kof) * 2;
                ldsm_x4(af[mt], bA + off);
            }
            #pragma unroll
            for (int nt2 = 0; nt2 < 4; nt2++) {
                uint32_t off = (uint32_t)((b_row4 + nt2 * 16) * BKP + ks + b_kof) * 2;
                uint32_t b4[4];
                ldsm_x4(b4, bB + off);
                #pragma unroll
                for (int mt = 0; mt < 2; mt++) {
                    mma_f16(acc[mt][nt2 * 2 + 0], af[mt], b4);
                    mma_f16(acc[mt][nt2 * 2 + 1], af[mt], b4 + 2);
                }
            }
        }
        __syncthreads();
    }

    const int er = lane >> 2;
    const int ec = (lane & 3) * 2;
    #pragma unroll
    for (int nt = 0; nt < 8; nt++) {
        int col = bn + warp_n * 64 + nt * 8 + ec;
        float bx = bias[col], by = bias[col + 1];
        #pragma unroll
        for (int mt = 0; mt < 2; mt++) {
            int r = bm + warp_m * 32 + mt * 16 + er;
            if (r < M) {
                float cx = acc[mt][nt][0] + bx, cy = acc[mt][nt][1] + by;
                if (WRITE_HALF) *(__half2*)&g_h[(size_t)r * HID + col] = __floats2half2_rn(cx, cy);
                else            *(float2*)&C_ext[(size_t)r * HID + col] = make_float2(cx, cy);
            }
            if (r + 8 < M) {
                float cx = acc[mt][nt][2] + bx, cy = acc[mt][nt][3] + by;
                if (WRITE_HALF) *(__half2*)&g_h[(size_t)(r + 8) * HID + col] = __floats2half2_rn(cx, cy);
                else            *(float2*)&C_ext[(size_t)(r + 8) * HID + col] = make_float2(cx, cy);
            }
        }
    }
}

// ================= launch =================
extern "C" void kernel_launch(void* const* d_in, const int* in_sizes, int n_in,
                              void* d_out, int out_size) {
    const float* x   = (const float*)d_in[0];
    const int*   ei  = (const int*)d_in[1];
    const float* W1  = (const float*)d_in[2];
    const float* b1  = (const float*)d_in[3];
    const float* W2  = (const float*)d_in[4];
    const float* b2  = (const float*)d_in[5];
    const float* W3  = (const float*)d_in[6];
    const float* b3  = (const float*)d_in[7];
    float*       out = (float*)d_out;

    const int E = in_sizes[1] / 2;
    const int* src = ei;
    const int* dst = ei + E;

    static bool attr_done = false;
    if (!attr_done) {
        cudaFuncSetAttribute(gemm_mma_kernel<128, true>,  cudaFuncAttributeMaxDynamicSharedMemorySize, GEMM_SMEM);
        cudaFuncSetAttribute(gemm_mma_kernel<256, true>,  cudaFuncAttributeMaxDynamicSharedMemorySize, GEMM_SMEM);
        cudaFuncSetAttribute(gemm_mma_kernel<256, false>, cudaFuncAttributeMaxDynamicSharedMemorySize, GEMM_SMEM);
        attr_done = true;
    }

    const int TB = 256;
    const int nb_nodes = (N_NODES + TB - 1) / TB;
    const int nb_edges = (E + TB - 1) / TB;
    const int nb_agg   = (N_NODES * 32 + TB - 1) / TB;
    dim3 gemm_grid((N_NODES + 127) / 128, 2);

    // preprocessing: CSR + dinv (parallel scan)
    init_kernel<<<nb_nodes, TB>>>();
    count_kernel<<<nb_edges, TB>>>(dst, E);
    dinv_kernel<<<nb_nodes, TB>>>();
    scan_reduce_kernel<<<NB_SCAN, 1024>>>();
    scan_part_kernel<<<1, 128>>>();
    scan_apply_kernel<<<NB_SCAN, 1024>>>();
    scatter_kernel<<<nb_edges, TB>>>(src, dst, E);

    // layer 1: x -> g_h fp16; agg -> g_a; gemm K=128 -> g_h
    xconv_kernel<<<(N_NODES * 128 / 4 + TB - 1) / TB, TB>>>(x);
    wconv_kernel<<<(HID * 128 + 255) / 256, 256>>>(W1, 128);
    agg_kernel<128, false><<<nb_agg, TB>>>();
    gemm_mma_kernel<128, true><<<gemm_grid, 256, GEMM_SMEM>>>(b1, nullptr);
    // layer 2
    wconv_kernel<<<(HID * 256 + 255) / 256, 256>>>(W2, 256);
    agg_kernel<256, true><<<nb_agg, TB>>>();
    gemm_mma_kernel<256, true><<<gemm_grid, 256, GEMM_SMEM>>>(b2, nullptr);
    // layer 3
    wconv_kernel<<<(HID * 256 + 255) / 256, 256>>>(W3, 256);
    agg_kernel<256, true><<<nb_agg, TB>>>();
    gemm_mma_kernel<256, false><<<gemm_grid, 256, GEMM_SMEM>>>(b3, out);
}

// round 16
// speedup vs baseline: 1.0500x; 1.0401x over previous
#include <cuda_runtime.h>
#include <cuda_fp16.h>
#include <cstdint>

#define N_NODES 100000
#define MAX_E   800000
#define HID     256
#define NB_SCAN 98          // ceil(100000/1024)

// ---- scratch (static __device__ globals; no allocation) ----
__device__ __align__(16) __half g_h[(size_t)N_NODES * HID];   // layer output, fp16
__device__ __align__(16) __half g_a[(size_t)N_NODES * HID];   // agg output = GEMM A, fp16
__device__ __align__(16) __half g_wt1[HID * 128];             // W1^T [256,128] fp16
__device__ __align__(16) __half g_wt2[HID * HID];             // W2^T [256,256] fp16
__device__ __align__(16) __half g_wt3[HID * HID];             // W3^T [256,256] fp16
__device__ float g_dinv[N_NODES];
__device__ int   g_cnt[N_NODES];
__device__ int   g_cur[N_NODES];
__device__ int   g_rowptr[N_NODES + 1];
__device__ int   g_col[MAX_E];
__device__ int   g_part[128];

template<int WSEL>
__device__ __forceinline__ const __half* sel_w() {
    if (WSEL == 1) return g_wt1;
    if (WSEL == 2) return g_wt2;
    return g_wt3;
}

// ================= PTX helpers (base-target only: ldmatrix/mma/cp.async) =================
__device__ __forceinline__ uint32_t smem_u32(const void* p) {
    uint32_t a;
    asm("{ .reg .u64 t; cvta.to.shared.u64 t, %1; cvt.u32.u64 %0, t; }" : "=r"(a) : "l"(p));
    return a;
}
__device__ __forceinline__ void ldsm_x4(uint32_t* r, uint32_t addr) {
    asm volatile("ldmatrix.sync.aligned.m8n8.x4.shared.b16 {%0,%1,%2,%3}, [%4];"
        : "=r"(r[0]), "=r"(r[1]), "=r"(r[2]), "=r"(r[3]) : "r"(addr));
}
__device__ __forceinline__ void ldsm_x2(uint32_t* r, uint32_t addr) {
    asm volatile("ldmatrix.sync.aligned.m8n8.x2.shared.b16 {%0,%1}, [%2];"
        : "=r"(r[0]), "=r"(r[1]) : "r"(addr));
}
__device__ __forceinline__ void mma_f16(float* c, const uint32_t* a, const uint32_t* b) {
    asm volatile("mma.sync.aligned.m16n8k16.row.col.f32.f16.f16.f32 "
        "{%0,%1,%2,%3}, {%4,%5,%6,%7}, {%8,%9}, {%0,%1,%2,%3};"
        : "+f"(c[0]), "+f"(c[1]), "+f"(c[2]), "+f"(c[3])
        : "r"(a[0]), "r"(a[1]), "r"(a[2]), "r"(a[3]), "r"(b[0]), "r"(b[1]));
}
__device__ __forceinline__ void cp16(uint32_t dst, const void* src) {
    asm volatile("cp.async.cg.shared.global [%0], [%1], 16;" :: "r"(dst), "l"(src));
}
#define CP_COMMIT() asm volatile("cp.async.commit_group;" ::: "memory")
#define CP_WAIT0()  asm volatile("cp.async.wait_group 0;" ::: "memory")

// ================= launch 0: init counters + convert all W (independent jobs) =================
__global__ void conv_init_kernel(const float* __restrict__ W1,
                                 const float* __restrict__ W2,
                                 const float* __restrict__ W3) {
    int i = blockIdx.x * blockDim.x + threadIdx.x;
    if (i < N_NODES) { g_cnt[i] = 0; g_cur[i] = 0; }
    if (i < HID * 128) {                      // W1^T: [256 n][128 k]
        int n = i / 128, k = i % 128;
        g_wt1[i] = __float2half_rn(W1[(size_t)k * HID + n]);
    }
    if (i < HID * HID) {                      // W2^T, W3^T: [256 n][256 k]
        int n = i / HID, k = i % HID;
        g_wt2[i] = __float2half_rn(W2[(size_t)k * HID + n]);
        g_wt3[i] = __float2half_rn(W3[(size_t)k * HID + n]);
    }
}

// ================= launch 1: degree count =================
__global__ void count_kernel(const int* __restrict__ dst, int E) {
    int e = blockIdx.x * blockDim.x + threadIdx.x;
    if (e < E) {
        int d = dst[e];
        if (d >= 0 && d < N_NODES) atomicAdd(&g_cnt[d], 1);
    }
}

// ================= launch 2: block sums + dinv =================
__global__ void scan_reduce_kernel() {
    __shared__ int ws[32];
    int t = threadIdx.x, lane = t & 31, wid = t >> 5;
    int i = blockIdx.x * 1024 + t;
    int v = (i < N_NODES) ? g_cnt[i] : 0;
    if (i < N_NODES) g_dinv[i] = rsqrtf((float)v + 1.0f);
    #pragma unroll
    for (int o = 16; o > 0; o >>= 1) v += __shfl_down_sync(0xffffffffu, v, o);
    if (lane == 0) ws[wid] = v;
    __syncthreads();
    if (wid == 0) {
        int s = ws[lane];
        #pragma unroll
        for (int o = 16; o > 0; o >>= 1) s += __shfl_down_sync(0xffffffffu, s, o);
        if (lane == 0) g_part[blockIdx.x] = s;
    }
}

// ================= launch 3: apply (each block scans the 98 partials inline) =================
// NOTE: all __syncthreads() executed by ALL threads (round-13 bug was divergent barriers)
__global__ void scan_apply_kernel() {
    __shared__ int ws[32];
    __shared__ int ws2[32];
    __shared__ int pexcl[128];     // exclusive prefix of block sums
    int t = threadIdx.x, lane = t & 31, wid = t >> 5;

    // phase A: exclusive scan of g_part[0..NB_SCAN). All warps run the shuffle
    // scan (results unused for wid>=4); barriers are block-uniform.
    int pv = (t < 128 && t < NB_SCAN) ? g_part[t] : 0;
    int pincl = pv;
    #pragma unroll
    for (int o = 1; o < 32; o <<= 1) {
        int n = __shfl_up_sync(0xffffffffu, pincl, o);
        if (lane >= o) pincl += n;
    }
    if (wid < 4 && lane == 31) ws[wid] = pincl;
    __syncthreads();
    if (t < 128) {
        int off = 0;
        for (int j = 0; j < wid; j++) off += ws[j];
        pexcl[t] = off + pincl - pv;
    }
    __syncthreads();

    // phase B: intra-block scan of g_cnt + block offset
    int i = blockIdx.x * 1024 + t;
    int v = (i < N_NODES) ? g_cnt[i] : 0;
    int incl = v;
    #pragma unroll
    for (int o = 1; o < 32; o <<= 1) {
        int n = __shfl_up_sync(0xffffffffu, incl, o);
        if (lane >= o) incl += n;
    }
    if (lane == 31) ws2[wid] = incl;
    __syncthreads();
    if (wid == 0) {
        int wv = ws2[lane];
        #pragma unroll
        for (int o = 1; o < 32; o <<= 1) {
            int n = __shfl_up_sync(0xffffffffu, wv, o);
            if (lane >= o) wv += n;
        }
        ws2[lane] = wv;
    }
    __syncthreads();
    int pre = (wid > 0) ? ws2[wid - 1] : 0;
    if (i < N_NODES) g_rowptr[i + 1] = pexcl[blockIdx.x] + pre + incl;
    if (i == 0) g_rowptr[0] = 0;
}

// ================= launch 4: scatter edges into CSR =================
__global__ void scatter_kernel(const int* __restrict__ src,
                               const int* __restrict__ dst, int E) {
    int e = blockIdx.x * blockDim.x + threadIdx.x;
    if (e < E) {
        int d = dst[e];
        int s = src[e];
        if (d >= 0 && d < N_NODES && s >= 0 && s < N_NODES) {
            int p = atomicAdd(&g_cur[d], 1);
            g_col[g_rowptr[d] + p] = s;
        }
    }
}

// ================= aggregation: g_a = fp16(A_norm @ act(in)) =================
// warp-per-node; IN_HALF: input g_h fp16, else external fp32 (layer 1)
template<int COLS, bool RELU, bool IN_HALF>
__global__ void agg_kernel(const float* __restrict__ in_ext) {
    int gw   = (blockIdx.x * blockDim.x + threadIdx.x) >> 5;
    int lane = threadIdx.x & 31;
    if (gw >= N_NODES) return;
    constexpr int V = COLS / 32;
    float acc[V];
    #pragma unroll
    for (int q = 0; q < V; q++) acc[q] = 0.f;
    const int base = lane * V;
    int rs = __ldg(&g_rowptr[gw]);
    int re = __ldg(&g_rowptr[gw + 1]);

    auto fetch = [&](int s, float vv[V]) {
        if (IN_HALF) {
            const __half* p = g_h + (size_t)s * COLS + base;
            if (V == 8) {
                uint4 raw = *(const uint4*)p;
                const __half2* h2 = reinterpret_cast<const __half2*>(&raw);
                #pragma unroll
                for (int j = 0; j < 4; j++) {
                    float2 f = __half22float2(h2[j]);
                    vv[2 * j] = f.x; vv[2 * j + 1] = f.y;
                }
            } else {
                uint2 raw = *(const uint2*)p;
                const __half2* h2 = reinterpret_cast<const __half2*>(&raw);
                #pragma unroll
                for (int j = 0; j < 2; j++) {
                    float2 f = __half22float2(h2[j]);
                    vv[2 * j] = f.x; vv[2 * j + 1] = f.y;
                }
            }
        } else {
            const float4* p = reinterpret_cast<const float4*>(in_ext + (size_t)s * COLS + base);
            #pragma unroll
            for (int q = 0; q < V / 4; q++) {
                float4 f = p[q];
                vv[q * 4 + 0] = f.x; vv[q * 4 + 1] = f.y;
                vv[q * 4 + 2] = f.z; vv[q * 4 + 3] = f.w;
            }
        }
        if (RELU) {
            #pragma unroll
            for (int q = 0; q < V; q++) vv[q] = fmaxf(vv[q], 0.f);
        }
    };

    int e = rs;
    for (; e + 3 < re; e += 4) {
        int s0 = g_col[e], s1 = g_col[e + 1], s2 = g_col[e + 2], s3 = g_col[e + 3];
        float w0 = g_dinv[s0], w1 = g_dinv[s1], w2 = g_dinv[s2], w3 = g_dinv[s3];
        float v0[V], v1[V], v2[V], v3[V];
        fetch(s0, v0); fetch(s1, v1); fetch(s2, v2); fetch(s3, v3);
        #pragma unroll
        for (int q = 0; q < V; q++)
            acc[q] += (w0 * v0[q] + w1 * v1[q]) + (w2 * v2[q] + w3 * v3[q]);
    }
    for (; e < re; e++) {
        int   s = g_col[e];
        float w = g_dinv[s];
        float v[V];
        fetch(s, v);
        #pragma unroll
        for (int q = 0; q < V; q++) acc[q] += w * v[q];
    }
    float di = g_dinv[gw];
    {
        float v[V];
        fetch(gw, v);
        #pragma unroll
        for (int q = 0; q < V; q++) acc[q] += di * v[q];
    }
    __half2 o[V / 2];
    #pragma unroll
    for (int q = 0; q < V / 2; q++)
        o[q] = __floats2half2_rn(acc[2 * q] * di, acc[2 * q + 1] * di);
    __half* po = g_a + (size_t)gw * COLS + base;
    if (V == 8)      *(uint4*)po = *(const uint4*)o;
    else             *(uint2*)po = *(const uint2*)o;
}

// ================= HMMA fp16 GEMM, CTA 128x128, cp.async 2-stage (round-9 best) =================
#define BKP       40
#define BUF_BYTES (128 * BKP * 2)
#define STG_BYTES (2 * BUF_BYTES)
#define GEMM_SMEM (2 * STG_BYTES)           // 40960 B -> 2 CTAs/SM

template<int K, int WSEL, bool WRITE_HALF>
__global__ __launch_bounds__(256)
void gemm_mma_kernel(const float* __restrict__ bias, float* __restrict__ C_ext) {
    extern __shared__ __align__(16) char dsm[];
    const __half* Wt = sel_w<WSEL>();
    const int M   = N_NODES;
    const int tid = threadIdx.x;
    const int wid = tid >> 5, lane = tid & 31;
    const int bm  = blockIdx.x * 128;
    const int bn  = blockIdx.y * 128;
    const int warp_m = wid & 3;
    const int warp_n = wid >> 2;
    constexpr int NCH = K / 32;

    const uint32_t sb = smem_u32(dsm);
    const int r0 = tid >> 2, s0 = tid & 3;
    const int r1 = r0 + 64;

    float acc[2][8][4];
    #pragma unroll
    for (int mt = 0; mt < 2; mt++)
        #pragma unroll
        for (int nt = 0; nt < 8; nt++)
            #pragma unroll
            for (int q = 0; q < 4; q++) acc[mt][nt][q] = 0.f;

    const int a_row = warp_m * 32 + (lane & 15);
    const int a_kof = (lane >> 4) * 8;
    const int b_row = warp_n * 64 + (lane & 7);
    const int b_kof = ((lane >> 3) & 1) * 8;

    int gr0 = bm + r0; if (gr0 > M - 1) gr0 = M - 1;
    int gr1 = bm + r1; if (gr1 > M - 1) gr1 = M - 1;

    auto issue = [&](int c, int st) {
        const int k0 = c * 32;
        uint32_t base = sb + st * STG_BYTES;
        uint32_t o0 = (uint32_t)(r0 * BKP + s0 * 8) * 2;
        uint32_t o1 = (uint32_t)(r1 * BKP + s0 * 8) * 2;
        cp16(base + 0 * BUF_BYTES + o0, &g_a[(size_t)gr0 * K + k0 + s0 * 8]);
        cp16(base + 0 * BUF_BYTES + o1, &g_a[(size_t)gr1 * K + k0 + s0 * 8]);
        cp16(base + 1 * BUF_BYTES + o0, &Wt[(size_t)(bn + r0) * K + k0 + s0 * 8]);
        cp16(base + 1 * BUF_BYTES + o1, &Wt[(size_t)(bn + r1) * K + k0 + s0 * 8]);
        CP_COMMIT();
    };

    issue(0, 0);
    for (int c = 0; c < NCH; c++) {
        const int st = c & 1;
        CP_WAIT0();
        __syncthreads();
        if (c + 1 < NCH) issue(c + 1, st ^ 1);

        uint32_t base = sb + st * STG_BYTES;
        uint32_t bA = base;
        uint32_t bB = base + BUF_BYTES;
        #pragma unroll
        for (int ks = 0; ks < 32; ks += 16) {
            uint32_t af[2][4];
            #pragma unroll
            for (int mt = 0; mt < 2; mt++) {
                uint32_t off = (uint32_t)((a_row + mt * 16) * BKP + ks + a_kof) * 2;
                ldsm_x4(af[mt], bA + off);
            }
            #pragma unroll
            for (int nt = 0; nt < 8; nt++) {
                uint32_t off = (uint32_t)((b_row + nt * 8) * BKP + ks + b_kof) * 2;
                uint32_t bf[2];
                ldsm_x2(bf, bB + off);
                #pragma unroll
                for (int mt = 0; mt < 2; mt++)
                    mma_f16(acc[mt][nt], af[mt], bf);
            }
        }
        __syncthreads();
    }

    const int er = lane >> 2;
    const int ec = (lane & 3) * 2;
    #pragma unroll
    for (int nt = 0; nt < 8; nt++) {
        int col = bn + warp_n * 64 + nt * 8 + ec;
        float bx = bias[col], by = bias[col + 1];
        #pragma unroll
        for (int mt = 0; mt < 2; mt++) {
            int r = bm + warp_m * 32 + mt * 16 + er;
            if (r < M) {
                float cx = acc[mt][nt][0] + bx, cy = acc[mt][nt][1] + by;
                if (WRITE_HALF) *(__half2*)&g_h[(size_t)r * HID + col] = __floats2half2_rn(cx, cy);
                else            *(float2*)&C_ext[(size_t)r * HID + col] = make_float2(cx, cy);
            }
            if (r + 8 < M) {
                float cx = acc[mt][nt][2] + bx, cy = acc[mt][nt][3] + by;
                if (WRITE_HALF) *(__half2*)&g_h[(size_t)(r + 8) * HID + col] = __floats2half2_rn(cx, cy);
                else            *(float2*)&C_ext[(size_t)(r + 8) * HID + col] = make_float2(cx, cy);
            }
        }
    }
}

// ================= launch =================
extern "C" void kernel_launch(void* const* d_in, const int* in_sizes, int n_in,
                              void* d_out, int out_size) {
    const float* x   = (const float*)d_in[0];
    const int*   ei  = (const int*)d_in[1];
    const float* W1  = (const float*)d_in[2];
    const float* b1  = (const float*)d_in[3];
    const float* W2  = (const float*)d_in[4];
    const float* b2  = (const float*)d_in[5];
    const float* W3  = (const float*)d_in[6];
    const float* b3  = (const float*)d_in[7];
    float*       out = (float*)d_out;

    const int E = in_sizes[1] / 2;
    const int* src = ei;
    const int* dst = ei + E;

    static bool attr_done = false;
    if (!attr_done) {
        cudaFuncSetAttribute(gemm_mma_kernel<128, 1, true>,  cudaFuncAttributeMaxDynamicSharedMemorySize, GEMM_SMEM);
        cudaFuncSetAttribute(gemm_mma_kernel<256, 2, true>,  cudaFuncAttributeMaxDynamicSharedMemorySize, GEMM_SMEM);
        cudaFuncSetAttribute(gemm_mma_kernel<256, 3, false>, cudaFuncAttributeMaxDynamicSharedMemorySize, GEMM_SMEM);
        attr_done = true;
    }

    const int TB = 256;
    const int nb_edges = (E + TB - 1) / TB;
    const int nb_agg   = (N_NODES * 32 + TB - 1) / TB;
    dim3 gemm_grid((N_NODES + 127) / 128, 2);

    // prep: 5 launches (agg1 is launch #5 -> ncu -s 5 captures it)
    conv_init_kernel<<<(N_NODES + TB - 1) / TB, TB>>>(W1, W2, W3);
    count_kernel<<<nb_edges, TB>>>(dst, E);
    scan_reduce_kernel<<<NB_SCAN, 1024>>>();
    scan_apply_kernel<<<NB_SCAN, 1024>>>();
    scatter_kernel<<<nb_edges, TB>>>(src, dst, E);

    // layer 1: agg fp32 x -> g_a; gemm K=128 (W1) -> g_h fp16
    agg_kernel<128, false, false><<<nb_agg, TB>>>(x);
    gemm_mma_kernel<128, 1, true><<<gemm_grid, 256, GEMM_SMEM>>>(b1, nullptr);
    // layer 2
    agg_kernel<256, true, true><<<nb_agg, TB>>>(nullptr);
    gemm_mma_kernel<256, 2, true><<<gemm_grid, 256, GEMM_SMEM>>>(b2, nullptr);
    // layer 3
    agg_kernel<256, true, true><<<nb_agg, TB>>>(nullptr);
    gemm_mma_kernel<256, 3, false><<<gemm_grid, 256, GEMM_SMEM>>>(b3, out);
}